// round 17
// baseline (speedup 1.0000x reference)
#include <cuda_runtime.h>
#include <math.h>

// Problem constants
#define BATCH 4
#define SEQ   4096
#define DDIM  256
#define HDIM  1024
#define TAPS  15
#define MROWS (BATCH*SEQ)   // 16384

// Tile config
#define BM 128
#define BN 128
#define BK 16
#define STAGES 4
#define AWORDS (BM*BK)      // 2048 words / stage (8KB)
#define BWORDS (BK*BN)      // 2048 words / stage (8KB)

// Scratch (device globals; referenced ONLY from device code — host-passing
// them gives the host shadow address on GB300/ATS).
__device__ float g_U  [MROWS * DDIM];
__device__ float g_Hh [MROWS * DDIM];
__device__ float g_Act[MROWS * HDIM];
__device__ float g_V  [MROWS * DDIM];

// ---------------------------------------------------------------------------
// cp.async helpers
// ---------------------------------------------------------------------------
__device__ __forceinline__ unsigned smem_u32p(const void* p) {
    return (unsigned)__cvta_generic_to_shared(p);
}
__device__ __forceinline__ void cp16(unsigned dst, const float* src) {
    asm volatile("cp.async.cg.shared.global [%0], [%1], 16;" :: "r"(dst), "l"(src));
}
__device__ __forceinline__ void cp16z(unsigned dst, const float* src, int sb) {
    asm volatile("cp.async.cg.shared.global [%0], [%1], 16, %2;" :: "r"(dst), "l"(src), "r"(sb));
}
#define CP_COMMIT() asm volatile("cp.async.commit_group;")
// STAGES=4: at iteration it, groups for slices it..it+2 are outstanding;
// allow <=2 pending so slice it is complete.
#define CP_WAITN()  asm volatile("cp.async.wait_group 2;")

__device__ __forceinline__ void mma8(float c[4], const unsigned a[4], const unsigned b[2]) {
    asm volatile(
        "mma.sync.aligned.m16n8k8.row.col.f32.tf32.tf32.f32 "
        "{%0,%1,%2,%3}, {%4,%5,%6,%7}, {%8,%9}, {%0,%1,%2,%3};\n"
        : "+f"(c[0]), "+f"(c[1]), "+f"(c[2]), "+f"(c[3])
        : "r"(a[0]), "r"(a[1]), "r"(a[2]), "r"(a[3]), "r"(b[0]), "r"(b[1]));
}

// ---------------------------------------------------------------------------
// Swizzled-layout compute of one BK=16 slice.
// A layout: word = row*16 + (((k>>2) ^ ((row>>1)&3))<<2) + (k&3).
// B layout: word = k*128 + (n ^ (8*(k&3))).
// Both conflict-free for the m16n8k8 fragment pattern (bank math verified).
// Warp layout: 8 warps = 2(m) x 4(n); warp tile 64x32 = 4x4 m16n8k8 frags.
// ---------------------------------------------------------------------------
__device__ __forceinline__ void compute_slice(const float* __restrict__ Asb,
                                              const float* __restrict__ Bsb,
                                              int m_w, int n_w, int lane,
                                              float acc[4][4][4])
{
    const int r  = lane >> 2;
    const int kq = lane & 3;
    const int cx = (r >> 1) & 3;               // A chunk xor (row-derived, invariant)
    const unsigned* A = (const unsigned*)Asb;
    const unsigned* B = (const unsigned*)Bsb;

#pragma unroll
    for (int ks = 0; ks < 2; ks++) {
        const int k0 = (((2 * ks + 0) ^ cx) << 2) + kq;   // j=0 word offset in row
        const int k1 = (((2 * ks + 1) ^ cx) << 2) + kq;   // j=1
        unsigned af[4][4], bf[4][2];
#pragma unroll
        for (int mi = 0; mi < 4; mi++) {
            const int row = m_w + mi * 16 + r;
            af[mi][0] = A[row * 16 + k0];
            af[mi][1] = A[(row + 8) * 16 + k0];
            af[mi][2] = A[row * 16 + k1];
            af[mi][3] = A[(row + 8) * 16 + k1];
        }
        const int kb0 = (8 * ks + kq) * 128;
        const int kb1 = (8 * ks + kq + 4) * 128;
#pragma unroll
        for (int ni = 0; ni < 4; ni++) {
            const int n = (n_w + ni * 8 + r) ^ (8 * kq);
            bf[ni][0] = B[kb0 + n];
            bf[ni][1] = B[kb1 + n];
        }
#pragma unroll
        for (int mi = 0; mi < 4; mi++)
#pragma unroll
            for (int ni = 0; ni < 4; ni++)
                mma8(acc[mi][ni], af[mi], bf[ni]);
    }
}

// Per-thread swizzled STS destinations. Each thread owns two ADJACENT logical
// 16B chunks (cn0, cn0+1). Swizzled slots are (cn0^X) and (cn0^X)^1 — the
// second chunk address is first ^ 16 BYTES (bit-4 flip), NOT first + 16.
__device__ __forceinline__ unsigned a_sts_base(const float* As0, int am, int ak0) {
    const int c0 = (ak0 >> 2) ^ ((am >> 1) & 3);
    return smem_u32p(As0 + am * 16 + (c0 << 2));
}
__device__ __forceinline__ unsigned b_sts_base(const float* Bs0, int bk, int bn0) {
    const int c0 = (bn0 >> 2) ^ (2 * (bk & 3));
    return smem_u32p(Bs0 + bk * 128 + (c0 << 2));
}

// ---------------------------------------------------------------------------
// Kernel 1: mix GEMM (causal local conv, im2col) + bias + residual -> g_U
// M=16384, K=15*256, N=256. Grid (128, 2), 256 threads.
// ---------------------------------------------------------------------------
__global__ void __launch_bounds__(256, 2) mix_gemm_tc(const float* __restrict__ x,
                                                      const float* __restrict__ w_mix,
                                                      const float* __restrict__ b_mix)
{
    __shared__ __align__(128) float As[STAGES][AWORDS];
    __shared__ __align__(128) float Bs[STAGES][BWORDS];

    const int tid  = threadIdx.x;
    const int lane = tid & 31, wid = tid >> 5;
    const int bm = blockIdx.x * BM, bn = blockIdx.y * BN;
    const int m_w = (wid >> 2) * 64, n_w = (wid & 3) * 32;

    const int bidx = bm / SEQ, n_base = bm % SEQ;
    const float* xb = x + (size_t)bidx * SEQ * DDIM;

    const int am = tid >> 1, ak0 = (tid & 1) * 8;
    const int bk = tid >> 4, bn0 = (tid & 15) * 8;
    const unsigned aDst = a_sts_base(As[0], am, ak0);
    const unsigned bDst = b_sts_base(Bs[0], bk, bn0);

    float acc[4][4][4];
#pragma unroll
    for (int i = 0; i < 4; i++)
#pragma unroll
        for (int j = 0; j < 4; j++)
#pragma unroll
            for (int q = 0; q < 4; q++) acc[i][j][q] = 0.0f;

    const int NIT = TAPS * (DDIM / BK);  // 240

    auto issue_load = [&](int it, int s) {
        const int tap = it >> 4;
        const int d0  = (it & 15) << 4;
        const int src = n_base + am + tap - 14;
        const int sb  = (src >= 0) ? 16 : 0;
        const float* gA = &xb[(size_t)(src >= 0 ? src : 0) * DDIM + d0 + ak0];
        const unsigned a = aDst + (unsigned)s * (AWORDS * 4);
        cp16z(a,       gA,     sb);
        cp16z(a ^ 16u, gA + 4, sb);
        const float* gB = w_mix + ((size_t)tap * DDIM + (d0 + bk)) * DDIM + bn + bn0;
        const unsigned b = bDst + (unsigned)s * (BWORDS * 4);
        cp16(b,       gB);
        cp16(b ^ 16u, gB + 4);
        CP_COMMIT();
    };

    for (int s = 0; s < STAGES - 1; s++) issue_load(s, s);
    for (int it = 0; it < NIT; ++it) {
        CP_WAITN();
        __syncthreads();
        const int nxt = it + STAGES - 1;
        if (nxt < NIT) issue_load(nxt, nxt % STAGES);
        else CP_COMMIT();
        compute_slice(As[it % STAGES], Bs[it % STAGES], m_w, n_w, lane, acc);
    }

    // epilogue: + b_mix + x residual -> g_U
#pragma unroll
    for (int mi = 0; mi < 4; mi++) {
        const int r0 = bm + m_w + mi * 16 + (lane >> 2);
#pragma unroll
        for (int ni = 0; ni < 4; ni++) {
            const int c = bn + n_w + ni * 8 + 2 * (lane & 3);
            float2 bb = *(const float2*)&b_mix[c];
            float2 x0 = *(const float2*)&x[(size_t)r0 * DDIM + c];
            float2 x1 = *(const float2*)&x[(size_t)(r0 + 8) * DDIM + c];
            float2 o0 = { acc[mi][ni][0] + bb.x + x0.x, acc[mi][ni][1] + bb.y + x0.y };
            float2 o1 = { acc[mi][ni][2] + bb.x + x1.x, acc[mi][ni][3] + bb.y + x1.y };
            *(float2*)&g_U[(size_t)r0 * DDIM + c] = o0;
            *(float2*)&g_U[(size_t)(r0 + 8) * DDIM + c] = o1;
        }
    }
}

// ---------------------------------------------------------------------------
// Kernel 3: FFN1 = gelu(h @ W1 + b_ff1). M=16384, K=256, N=1024. Grid (128, 8).
// ---------------------------------------------------------------------------
__global__ void __launch_bounds__(256, 2) ffn1_tc(const float* __restrict__ W1,
                                                  const float* __restrict__ bff1)
{
    __shared__ __align__(128) float As[STAGES][AWORDS];
    __shared__ __align__(128) float Bs[STAGES][BWORDS];

    const int tid  = threadIdx.x;
    const int lane = tid & 31, wid = tid >> 5;
    const int bm = blockIdx.x * BM, bn = blockIdx.y * BN;
    const int m_w = (wid >> 2) * 64, n_w = (wid & 3) * 32;

    const int am = tid >> 1, ak0 = (tid & 1) * 8;
    const int bk = tid >> 4, bn0 = (tid & 15) * 8;
    const unsigned aDst = a_sts_base(As[0], am, ak0);
    const unsigned bDst = b_sts_base(Bs[0], bk, bn0);

    float acc[4][4][4];
#pragma unroll
    for (int i = 0; i < 4; i++)
#pragma unroll
        for (int j = 0; j < 4; j++)
#pragma unroll
            for (int q = 0; q < 4; q++) acc[i][j][q] = 0.0f;

    const int NIT = DDIM / BK;  // 16

    auto issue_load = [&](int it, int s) {
        const int k0 = it << 4;
        const float* gA = &g_Hh[(size_t)(bm + am) * DDIM + k0 + ak0];
        const unsigned a = aDst + (unsigned)s * (AWORDS * 4);
        cp16(a,       gA);
        cp16(a ^ 16u, gA + 4);
        const float* gB = &W1[(size_t)(k0 + bk) * HDIM + bn + bn0];
        const unsigned b = bDst + (unsigned)s * (BWORDS * 4);
        cp16(b,       gB);
        cp16(b ^ 16u, gB + 4);
        CP_COMMIT();
    };

    for (int s = 0; s < STAGES - 1; s++) issue_load(s, s);
    for (int it = 0; it < NIT; ++it) {
        CP_WAITN();
        __syncthreads();
        const int nxt = it + STAGES - 1;
        if (nxt < NIT) issue_load(nxt, nxt % STAGES);
        else CP_COMMIT();
        compute_slice(As[it % STAGES], Bs[it % STAGES], m_w, n_w, lane, acc);
    }

    const float kInvSqrt2 = 0.70710678118654752f;
#pragma unroll
    for (int mi = 0; mi < 4; mi++) {
        const int r0 = bm + m_w + mi * 16 + (lane >> 2);
#pragma unroll
        for (int ni = 0; ni < 4; ni++) {
            const int c = bn + n_w + ni * 8 + 2 * (lane & 3);
            float2 bb = *(const float2*)&bff1[c];
            float v00 = acc[mi][ni][0] + bb.x;
            float v01 = acc[mi][ni][1] + bb.y;
            float v10 = acc[mi][ni][2] + bb.x;
            float v11 = acc[mi][ni][3] + bb.y;
            float2 o0 = { 0.5f * v00 * (1.0f + erff(v00 * kInvSqrt2)),
                          0.5f * v01 * (1.0f + erff(v01 * kInvSqrt2)) };
            float2 o1 = { 0.5f * v10 * (1.0f + erff(v10 * kInvSqrt2)),
                          0.5f * v11 * (1.0f + erff(v11 * kInvSqrt2)) };
            *(float2*)&g_Act[(size_t)r0 * HDIM + c] = o0;
            *(float2*)&g_Act[(size_t)(r0 + 8) * HDIM + c] = o1;
        }
    }
}

// ---------------------------------------------------------------------------
// Kernel 4: FFN2 = Act @ W2 + b_ff2 + h. M=16384, K=1024, N=256. Grid (128, 2).
// ---------------------------------------------------------------------------
__global__ void __launch_bounds__(256, 2) ffn2_tc(const float* __restrict__ W2,
                                                  const float* __restrict__ bff2)
{
    __shared__ __align__(128) float As[STAGES][AWORDS];
    __shared__ __align__(128) float Bs[STAGES][BWORDS];

    const int tid  = threadIdx.x;
    const int lane = tid & 31, wid = tid >> 5;
    const int bm = blockIdx.x * BM, bn = blockIdx.y * BN;
    const int m_w = (wid >> 2) * 64, n_w = (wid & 3) * 32;

    const int am = tid >> 1, ak0 = (tid & 1) * 8;
    const int bk = tid >> 4, bn0 = (tid & 15) * 8;
    const unsigned aDst = a_sts_base(As[0], am, ak0);
    const unsigned bDst = b_sts_base(Bs[0], bk, bn0);

    float acc[4][4][4];
#pragma unroll
    for (int i = 0; i < 4; i++)
#pragma unroll
        for (int j = 0; j < 4; j++)
#pragma unroll
            for (int q = 0; q < 4; q++) acc[i][j][q] = 0.0f;

    const int NIT = HDIM / BK;  // 64

    auto issue_load = [&](int it, int s) {
        const int k0 = it << 4;
        const float* gA = &g_Act[(size_t)(bm + am) * HDIM + k0 + ak0];
        const unsigned a = aDst + (unsigned)s * (AWORDS * 4);
        cp16(a,       gA);
        cp16(a ^ 16u, gA + 4);
        const float* gB = &W2[(size_t)(k0 + bk) * DDIM + bn + bn0];
        const unsigned b = bDst + (unsigned)s * (BWORDS * 4);
        cp16(b,       gB);
        cp16(b ^ 16u, gB + 4);
        CP_COMMIT();
    };

    for (int s = 0; s < STAGES - 1; s++) issue_load(s, s);
    for (int it = 0; it < NIT; ++it) {
        CP_WAITN();
        __syncthreads();
        const int nxt = it + STAGES - 1;
        if (nxt < NIT) issue_load(nxt, nxt % STAGES);
        else CP_COMMIT();
        compute_slice(As[it % STAGES], Bs[it % STAGES], m_w, n_w, lane, acc);
    }

    // epilogue: + b_ff2 + h residual -> g_V
#pragma unroll
    for (int mi = 0; mi < 4; mi++) {
        const int r0 = bm + m_w + mi * 16 + (lane >> 2);
#pragma unroll
        for (int ni = 0; ni < 4; ni++) {
            const int c = bn + n_w + ni * 8 + 2 * (lane & 3);
            float2 bb = *(const float2*)&bff2[c];
            float2 h0 = *(const float2*)&g_Hh[(size_t)r0 * DDIM + c];
            float2 h1 = *(const float2*)&g_Hh[(size_t)(r0 + 8) * DDIM + c];
            float2 o0 = { acc[mi][ni][0] + bb.x + h0.x, acc[mi][ni][1] + bb.y + h0.y };
            float2 o1 = { acc[mi][ni][2] + bb.x + h1.x, acc[mi][ni][3] + bb.y + h1.y };
            *(float2*)&g_V[(size_t)r0 * DDIM + c] = o0;
            *(float2*)&g_V[(size_t)(r0 + 8) * DDIM + c] = o1;
        }
    }
}

// ---------------------------------------------------------------------------
// LayerNorm over last dim (256). One 256-thread block per row.
// ---------------------------------------------------------------------------
__device__ __forceinline__ void ln_row(const float* __restrict__ in,
                                       const float* __restrict__ g,
                                       const float* __restrict__ b,
                                       float* __restrict__ out)
{
    const int row = blockIdx.x;
    const int t   = threadIdx.x;
    float v = in[(size_t)row * DDIM + t];

    float s = v;
#pragma unroll
    for (int o = 16; o > 0; o >>= 1) s += __shfl_xor_sync(0xffffffffu, s, o);
    __shared__ float r1[8], r2[8];
    if ((t & 31) == 0) r1[t >> 5] = s;
    __syncthreads();
    float tot = 0.0f;
#pragma unroll
    for (int i = 0; i < 8; i++) tot += r1[i];
    const float mu = tot * (1.0f / 256.0f);

    const float d = v - mu;
    float s2 = d * d;
#pragma unroll
    for (int o = 16; o > 0; o >>= 1) s2 += __shfl_xor_sync(0xffffffffu, s2, o);
    if ((t & 31) == 0) r2[t >> 5] = s2;
    __syncthreads();
    float tv = 0.0f;
#pragma unroll
    for (int i = 0; i < 8; i++) tv += r2[i];
    const float var = tv * (1.0f / 256.0f);

    out[(size_t)row * DDIM + t] = d * rsqrtf(var + 1e-5f) * g[t] + b[t];
}

__global__ void ln1_kernel(const float* __restrict__ g, const float* __restrict__ b)
{
    ln_row(g_U, g, b, g_Hh);
}

__global__ void ln2_kernel(const float* __restrict__ g, const float* __restrict__ b,
                           float* __restrict__ out)
{
    ln_row(g_V, g, b, out);
}

// ---------------------------------------------------------------------------
extern "C" void kernel_launch(void* const* d_in, const int* in_sizes, int n_in,
                              void* d_out, int out_size)
{
    const float* x     = (const float*)d_in[0];
    const float* w_mix = (const float*)d_in[1];
    const float* b_mix = (const float*)d_in[2];
    const float* g1    = (const float*)d_in[3];
    const float* b1    = (const float*)d_in[4];
    const float* w_ff1 = (const float*)d_in[5];
    const float* b_ff1 = (const float*)d_in[6];
    const float* w_ff2 = (const float*)d_in[7];
    const float* b_ff2 = (const float*)d_in[8];
    const float* g2    = (const float*)d_in[9];
    const float* b2    = (const float*)d_in[10];
    float* out = (float*)d_out;

    dim3 block(256);

    mix_gemm_tc<<<dim3(MROWS / BM, DDIM / BN), block>>>(x, w_mix, b_mix);
    ln1_kernel<<<MROWS, 256>>>(g1, b1);
    ffn1_tc<<<dim3(MROWS / BM, HDIM / BN), block>>>(w_ff1, b_ff1);
    ffn2_tc<<<dim3(MROWS / BM, DDIM / BN), block>>>(w_ff2, b_ff2);
    ln2_kernel<<<MROWS, 256>>>(g2, b2, out);
}